// round 11
// baseline (speedup 1.0000x reference)
#include <cuda_runtime.h>
#include <cuda_fp16.h>
#include <math.h>

#define NN    8192
#define DIN   128
#define HDIM  256
#define NWORD 256               // 8192/32 mask words per row
#define NTILE 64                // 8192/128 tile grid
#define NUT   2080              // upper-triangle tile count (64*65/2)
#define KRANK 63753420u         // nearest-rank index of 0.95 quantile over N*N values
#define CAND_CAP (1u << 24)     // 16M candidate slots (64 MB)

typedef unsigned long long u64;

// packed f32x2 helpers (sm_103a): 2 independent fp32 FMAs per instruction, bit-identical
#define FMA2(d, a, b)   asm("fma.rn.f32x2 %0, %1, %2, %0;" : "+l"(d) : "l"(a), "l"(b))
#define DUP2(d, s)      asm("mov.b64 %0, {%1, %1};" : "=l"(d) : "f"(s))
#define UNPK(lo, hi, s) asm("mov.b64 {%0, %1}, %2;" : "=f"(lo), "=f"(hi) : "l"(s))

// ----------------- device scratch (static globals; no runtime allocation) -----------------
__device__ float    g_xn  [NN * DIN];          // normalized x            (4 MB)
__device__ float    g_sim [(size_t)NN * NN];   // |xn@xn^T|, UPPER TILES ONLY valid
__device__ unsigned g_adj [NN * NWORD];        // adjacency bitmask       (8 MB)
__device__ float    g_inv [NN];                // 1/deg
__device__ float    g_h0  [NN * HDIM];
__device__ float    g_h1  [NN * HDIM];
__device__ float    g_h2  [NN * HDIM];
__device__ __half   g_h0f [NN * HDIM];         // fp16 copy for aggregation
__device__ __half   g_h1f [NN * HDIM];
__device__ float    g_agg [NN * HDIM];
__device__ float    g_yl  [NN];
__device__ float    g_yr  [NN];
__device__ float    g_sc  [NN];
__device__ float    g_o1v [NN];
__device__ unsigned g_hist[8192];
__device__ unsigned g_cand[CAND_CAP];          // compacted pass-1 candidates (64 MB)
__device__ unsigned g_cnt;
__device__ unsigned g_key;
__device__ unsigned g_rem;

// decode linear upper-triangle tile index -> (bi, bj), bi <= bj
__device__ __forceinline__ void tile_decode(int tl, int& bi, int& bj) {
    int b = 0, rem = tl;
    while (rem >= NTILE - b) { rem -= NTILE - b; b++; }
    bi = b; bj = b + rem;
}

// ----------------- 1. row-normalize x (clamp norm at 1e-8) -----------------
__global__ void k_normalize(const float* __restrict__ x) {
    int row = blockIdx.x;
    int t   = threadIdx.x;                 // 128 threads = 1 col each
    float v = x[row * DIN + t];
    float s = v * v;
    #pragma unroll
    for (int o = 16; o; o >>= 1) s += __shfl_xor_sync(0xffffffffu, s, o);
    __shared__ float ws[4];
    if ((t & 31) == 0) ws[t >> 5] = s;
    __syncthreads();
    float nrm = fmaxf(sqrtf(ws[0] + ws[1] + ws[2] + ws[3]), 1e-8f);
    g_xn[row * DIN + t] = v / nrm;
}

// ----------------- 2. sim = |xn @ xn^T|, upper-triangle tiles ONLY, FFMA2 inner ---------
__global__ void __launch_bounds__(256, 2) k_simgemm_sym() {
    const int bi = blockIdx.x, bj = blockIdx.y;
    if (bj < bi) return;                       // only upper tiles computed & stored

    __shared__ float As[16][132];
    __shared__ float Bs[16][132];

    const int t  = threadIdx.x;
    const int tx = t & 15, ty = t >> 4;
    const int r0 = bi * 128, c0 = bj * 128;

    u64 acc2[8][4];                            // {acc[i][2j], acc[i][2j+1]} packed pairs
    #pragma unroll
    for (int i = 0; i < 8; i++)
        #pragma unroll
        for (int j = 0; j < 4; j++) acc2[i][j] = 0ull;

    for (int k0 = 0; k0 < DIN; k0 += 16) {
        #pragma unroll
        for (int i = 0; i < 2; i++) {
            int lid = t + i * 256;              // 0..511
            int row = lid >> 2;                 // 0..127
            int q   = lid & 3;
            float4 a = *(const float4*)(g_xn + (size_t)(r0 + row) * DIN + k0 + q * 4);
            As[q*4+0][row] = a.x; As[q*4+1][row] = a.y;
            As[q*4+2][row] = a.z; As[q*4+3][row] = a.w;
            float4 b = *(const float4*)(g_xn + (size_t)(c0 + row) * DIN + k0 + q * 4);
            Bs[q*4+0][row] = b.x; Bs[q*4+1][row] = b.y;
            Bs[q*4+2][row] = b.z; Bs[q*4+3][row] = b.w;
        }
        __syncthreads();
        #pragma unroll
        for (int kk = 0; kk < 16; kk++) {
            float a[8];
            *(float4*)&a[0] = *(const float4*)&As[kk][ty * 4];
            *(float4*)&a[4] = *(const float4*)&As[kk][64 + ty * 4];
            u64 bv[4];
            {
                const u64* bp0 = (const u64*)&Bs[kk][tx * 4];
                const u64* bp1 = (const u64*)&Bs[kk][64 + tx * 4];
                bv[0] = bp0[0]; bv[1] = bp0[1];
                bv[2] = bp1[0]; bv[3] = bp1[1];
            }
            #pragma unroll
            for (int i = 0; i < 8; i++) {
                u64 a2; DUP2(a2, a[i]);
                FMA2(acc2[i][0], a2, bv[0]);
                FMA2(acc2[i][1], a2, bv[1]);
                FMA2(acc2[i][2], a2, bv[2]);
                FMA2(acc2[i][3], a2, bv[3]);
            }
        }
        __syncthreads();
    }
    #pragma unroll
    for (int i = 0; i < 8; i++) {
        int row = r0 + ((i >> 2) << 6) + ty * 4 + (i & 3);
        float* dst = g_sim + (size_t)row * NN + c0;
        float v[8];
        #pragma unroll
        for (int j = 0; j < 4; j++) UNPK(v[2*j], v[2*j+1], acc2[i][j]);
        *(float4*)(dst + tx * 4) =
            make_float4(fabsf(v[0]), fabsf(v[1]), fabsf(v[2]), fabsf(v[3]));
        *(float4*)(dst + 64 + tx * 4) =
            make_float4(fabsf(v[4]), fabsf(v[5]), fabsf(v[6]), fabsf(v[7]));
    }
}

// ----------------- 3. exact k-th order statistic: radix select over UPPER tiles ---------
// Pass 0: bits[31:19]. Pass 1: bits[18:6] + candidate compaction (weight-expanded).
// Pass 2: bits[5:0] over compacted candidates only.
__global__ void k_init_sel() {
    if (threadIdx.x == 0 && blockIdx.x == 0) { g_key = 0u; g_rem = KRANK; g_cnt = 0u; }
    int i = blockIdx.x * blockDim.x + threadIdx.x;
    if (i < 8192) g_hist[i] = 0u;
}

template <int PASS>
__global__ void k_hist() {
    __shared__ unsigned sh[8192];
    for (int i = threadIdx.x; i < 8192; i += blockDim.x) sh[i] = 0u;
    __syncthreads();
    const unsigned key = g_key;
    const unsigned kp1 = key >> 19;
    const int t = threadIdx.x;
    for (int tl = blockIdx.x; tl < NUT; tl += gridDim.x) {
        int bi, bj; tile_decode(tl, bi, bj);
        const unsigned wgt = (bi == bj) ? 1u : 2u;
        const size_t base = (size_t)bi * 128 * NN + bj * 128;
        #pragma unroll 4
        for (int i = 0; i < 16; i++) {
            int lin = i * 256 + t;
            int r = lin >> 5, c = lin & 31;
            float4 v = __ldg((const float4*)(g_sim + base + (size_t)r * NN) + c);
            float vv[4] = {v.x, v.y, v.z, v.w};
            #pragma unroll
            for (int u = 0; u < 4; u++) {
                unsigned b = __float_as_uint(vv[u]);
                if (PASS == 0) {
                    atomicAdd(&sh[b >> 19], wgt);
                } else {
                    if ((b >> 19) == kp1) {
                        atomicAdd(&sh[(b >> 6) & 8191u], wgt);
                        unsigned idx = atomicAdd(&g_cnt, wgt);
                        if (idx + wgt <= CAND_CAP) {
                            g_cand[idx] = b;
                            if (wgt == 2u) g_cand[idx + 1] = b;
                        }
                    }
                }
            }
        }
    }
    __syncthreads();
    for (int i = threadIdx.x; i < 8192; i += blockDim.x) {
        unsigned c = sh[i];
        if (c) atomicAdd(&g_hist[i], c);
    }
}

// pass 2 over compacted candidates (already weight-expanded)
__global__ void k_hist2c() {
    __shared__ unsigned sh[64];
    if (threadIdx.x < 64) sh[threadIdx.x] = 0u;
    __syncthreads();
    const unsigned kp2 = g_key >> 6;
    unsigned n = g_cnt; if (n > CAND_CAP) n = CAND_CAP;
    for (unsigned i = blockIdx.x * blockDim.x + threadIdx.x; i < n; i += gridDim.x * blockDim.x) {
        unsigned b = g_cand[i];
        if ((b >> 6) == kp2) atomicAdd(&sh[b & 63u], 1u);
    }
    __syncthreads();
    if (threadIdx.x < 64) {
        unsigned c = sh[threadIdx.x];
        if (c) atomicAdd(&g_hist[threadIdx.x], c);
    }
}

// parallel-prefix scan: 1024 threads, shfl warp-scan + 32-word combine
__global__ void __launch_bounds__(1024) k_scan(int nbins, int shift) {
    __shared__ unsigned s[8192];
    __shared__ unsigned wsum[32];
    int t = threadIdx.x;                    // 1024 threads, single block
    for (int i = t; i < nbins; i += 1024) s[i] = g_hist[i];
    __syncthreads();
    int per = (nbins + 1023) / 1024;
    int lo = t * per; if (lo > nbins) lo = nbins;
    int hi = lo + per; if (hi > nbins) hi = nbins;
    unsigned mysum = 0;
    for (int i = lo; i < hi; i++) mysum += s[i];
    // inclusive warp scan
    unsigned inc = mysum;
    #pragma unroll
    for (int o = 1; o < 32; o <<= 1) {
        unsigned v = __shfl_up_sync(0xffffffffu, inc, o);
        if ((t & 31) >= o) inc += v;
    }
    if ((t & 31) == 31) wsum[t >> 5] = inc;
    __syncthreads();
    unsigned wpre = 0;
    #pragma unroll
    for (int i = 0; i < 32; i++) if (i < (t >> 5)) wpre += wsum[i];
    unsigned pre = wpre + inc - mysum;      // exclusive prefix for this thread
    unsigned rem = g_rem;
    __syncthreads();                        // all read g_rem before the winner writes it
    if (mysum > 0 && rem >= pre && rem < pre + mysum) {
        unsigned r = rem - pre;
        for (int i = lo; i < hi; i++) {
            if (r < s[i]) { g_key |= ((unsigned)i) << shift; g_rem = r; break; }
            r -= s[i];
        }
    }
    __syncthreads();
    for (int i = t; i < nbins; i += 1024) g_hist[i] = 0u;  // ready for next pass / replay
}

// ----------------- 4. adjacency from upper tiles: direct + bit-transposed mirror --------
__global__ void __launch_bounds__(256) k_adj_tile() {
    __shared__ unsigned bits[128][4];
    int bi, bj; tile_decode(blockIdx.x, bi, bj);
    const int t = threadIdx.x, lane = t & 31, w = t >> 5;   // 8 warps
    const float eps = __uint_as_float(g_key);
    const int r0 = bi * 128, c0 = bj * 128;
    const int cw0 = c0 >> 5, rw0 = r0 >> 5;

    #pragma unroll
    for (int rr = 0; rr < 16; rr++) {
        int r = w * 16 + rr;
        const float* srow = g_sim + (size_t)(r0 + r) * NN + c0;
        #pragma unroll
        for (int q = 0; q < 4; q++) {
            float v = srow[q * 32 + lane];
            unsigned m = __ballot_sync(0xffffffffu, v >= eps);
            if (lane == 0) {
                g_adj[(r0 + r) * NWORD + cw0 + q] = m;
                bits[r][q] = m;
            }
        }
    }
    if (bi == bj) return;
    __syncthreads();

    const int qr = w >> 1;                  // warps 0..7 -> qr 0..3
    const int chalf = (w & 1) * 64;         // c range [chalf, chalf+64)
    unsigned wa = bits[qr * 32 + lane][(chalf >> 5) + 0];
    unsigned wb = bits[qr * 32 + lane][(chalf >> 5) + 1];
    #pragma unroll
    for (int cc = 0; cc < 32; cc++) {
        unsigned m = __ballot_sync(0xffffffffu, (wa >> cc) & 1u);
        if (lane == 0) g_adj[(c0 + chalf + cc) * NWORD + rw0 + qr] = m;
    }
    #pragma unroll
    for (int cc = 0; cc < 32; cc++) {
        unsigned m = __ballot_sync(0xffffffffu, (wb >> cc) & 1u);
        if (lane == 0) g_adj[(c0 + chalf + 32 + cc) * NWORD + rw0 + qr] = m;
    }
}

// ----------------- 4b. degrees: popc over adjacency rows -----------------
__global__ void k_deg() {
    int row  = (blockIdx.x * blockDim.x + threadIdx.x) >> 5;  // one warp / row
    int lane = threadIdx.x & 31;
    if (row >= NN) return;
    const unsigned* ar = g_adj + row * NWORD;
    int cnt = 0;
    #pragma unroll
    for (int i = 0; i < 8; i++) cnt += __popc(ar[lane + i * 32]);
    #pragma unroll
    for (int o = 16; o; o >>= 1) cnt += __shfl_xor_sync(0xffffffffu, cnt, o);
    if (lane == 0) g_inv[row] = 1.0f / fmaxf((float)cnt, 1.0f);
}

// ----------------- 5. fused dense / SAGE GEMM, FFMA2 inner ------------------------------
__global__ void __launch_bounds__(256) k_sage(
    const float* __restrict__ A1, const float* __restrict__ W1, int K1,
    const float* __restrict__ A2, const float* __restrict__ W2, int K2,
    const float* __restrict__ bias, const float* __restrict__ res,
    float* __restrict__ out, __half* __restrict__ out16, int relu)
{
    __shared__ float As[16][132];
    __shared__ float Bs[16][68];
    const int t  = threadIdx.x;
    const int tx = t & 15, ty = t >> 4;
    const int r0 = blockIdx.x * 128, c0 = blockIdx.y * 64;

    u64 acc2[8][2];
    #pragma unroll
    for (int i = 0; i < 8; i++) { acc2[i][0] = 0ull; acc2[i][1] = 0ull; }

    const float* Ap = A1; const float* Wp = W1; int K = K1;
    for (int phase = 0; phase < 2; phase++) {
        if (phase == 1) {
            if (A2 == nullptr) break;
            Ap = A2; Wp = W2; K = K2;
        }
        for (int k0 = 0; k0 < K; k0 += 16) {
            #pragma unroll
            for (int i = 0; i < 2; i++) {
                int lid = t + i * 256;
                int row = lid >> 2;             // 0..127
                int q   = lid & 3;
                float4 a = *(const float4*)(Ap + (size_t)(r0 + row) * K + k0 + q * 4);
                As[q*4+0][row] = a.x; As[q*4+1][row] = a.y;
                As[q*4+2][row] = a.z; As[q*4+3][row] = a.w;
            }
            {
                int kk = t >> 4, n4 = (t & 15) * 4;
                float4 b = *(const float4*)(Wp + (size_t)(k0 + kk) * HDIM + c0 + n4);
                Bs[kk][n4+0] = b.x; Bs[kk][n4+1] = b.y;
                Bs[kk][n4+2] = b.z; Bs[kk][n4+3] = b.w;
            }
            __syncthreads();
            #pragma unroll
            for (int kk = 0; kk < 16; kk++) {
                float a[8];
                *(float4*)&a[0] = *(const float4*)&As[kk][ty * 4];
                *(float4*)&a[4] = *(const float4*)&As[kk][64 + ty * 4];
                u64 bv[2];
                {
                    const u64* bp = (const u64*)&Bs[kk][tx * 4];
                    bv[0] = bp[0]; bv[1] = bp[1];
                }
                #pragma unroll
                for (int i = 0; i < 8; i++) {
                    u64 a2; DUP2(a2, a[i]);
                    FMA2(acc2[i][0], a2, bv[0]);
                    FMA2(acc2[i][1], a2, bv[1]);
                }
            }
            __syncthreads();
        }
    }
    float bvv[4];
    *(float4*)bvv = *(const float4*)(bias + c0 + tx * 4);
    #pragma unroll
    for (int i = 0; i < 8; i++) {
        int row = r0 + ((i >> 2) << 6) + ty * 4 + (i & 3);
        float v[4];
        UNPK(v[0], v[1], acc2[i][0]);
        UNPK(v[2], v[3], acc2[i][1]);
        #pragma unroll
        for (int j = 0; j < 4; j++) v[j] += bvv[j];
        if (res) {
            float4 rr = *(const float4*)(res + (size_t)row * HDIM + c0 + tx * 4);
            v[0] += rr.x; v[1] += rr.y; v[2] += rr.z; v[3] += rr.w;
        }
        if (relu) {
            #pragma unroll
            for (int j = 0; j < 4; j++) v[j] = fmaxf(v[j], 0.f);
        }
        *(float4*)(out + (size_t)row * HDIM + c0 + tx * 4) = make_float4(v[0], v[1], v[2], v[3]);
        if (out16) {
            __half2 h01 = __floats2half2_rn(v[0], v[1]);
            __half2 h23 = __floats2half2_rn(v[2], v[3]);
            uint2 pk;
            pk.x = *(unsigned*)&h01;
            pk.y = *(unsigned*)&h23;
            *(uint2*)(out16 + (size_t)row * HDIM + c0 + tx * 4) = pk;
        }
    }
}

// ----------------- 6. mean aggregation, width 256, fp16 input, fp32 accumulate ----------
// 512 threads = 8 groups x 64; each group scans 32 mask words (half the serial chain of R6)
__global__ void __launch_bounds__(512) k_agg(const __half* __restrict__ h, float* __restrict__ out) {
    __shared__ unsigned sm[NWORD];
    __shared__ float red[8][HDIM];
    int row = blockIdx.x;
    int t   = threadIdx.x;
    int g   = t >> 6;                       // group 0..7 (its own 32 mask words)
    int c4  = t & 63;                       // this thread's 4-column slot
    if (t < NWORD) sm[t] = g_adj[row * NWORD + t];
    __syncthreads();
    float4 acc = make_float4(0.f, 0.f, 0.f, 0.f);
    for (int w = g * 32; w < g * 32 + 32; w++) {
        unsigned m = sm[w];
        int base = w << 5;
        while (m) {
            int b0 = __ffs(m) - 1; m &= m - 1;
            uint2 r0 = __ldg((const uint2*)(h + ((size_t)(base + b0) << 8)) + c4);
            if (m) {
                int b1 = __ffs(m) - 1; m &= m - 1;
                uint2 r1 = __ldg((const uint2*)(h + ((size_t)(base + b1) << 8)) + c4);
                float2 a0 = __half22float2(*(__half2*)&r0.x);
                float2 a1 = __half22float2(*(__half2*)&r0.y);
                float2 b0v = __half22float2(*(__half2*)&r1.x);
                float2 b1v = __half22float2(*(__half2*)&r1.y);
                acc.x += a0.x + b0v.x; acc.y += a0.y + b0v.y;
                acc.z += a1.x + b1v.x; acc.w += a1.y + b1v.y;
            } else {
                float2 a0 = __half22float2(*(__half2*)&r0.x);
                float2 a1 = __half22float2(*(__half2*)&r0.y);
                acc.x += a0.x; acc.y += a0.y;
                acc.z += a1.x; acc.w += a1.y;
            }
        }
    }
    ((float4*)red[g])[c4] = acc;
    __syncthreads();
    if (t < 64) {
        float4 r = make_float4(0.f, 0.f, 0.f, 0.f);
        #pragma unroll
        for (int gg = 0; gg < 8; gg++) {
            float4 a = ((float4*)red[gg])[t];
            r.x += a.x; r.y += a.y; r.z += a.z; r.w += a.w;
        }
        float inv = g_inv[row];
        r.x *= inv; r.y *= inv; r.z *= inv; r.w *= inv;
        ((float4*)(out + ((size_t)row << 8)))[t] = r;
    }
}

// ----------------- 7. width-1 aggregation with fused epilogues -----------------
// mode 0: g_o1v[row] = relu(agg1(y)[row] + p0 + g_yr[row])
// mode 1: out[row]   = sigmoid(agg1(y)[row]*p0 + p1 + y[row]*p2 + g_sc[row])
template <int MODE>
__global__ void __launch_bounds__(256) k_agg1f(const float* __restrict__ y,
                                               const float* __restrict__ w0,
                                               const float* __restrict__ w1,
                                               const float* __restrict__ w2,
                                               float* __restrict__ out) {
    __shared__ float sred[8];
    int row = blockIdx.x, t = threadIdx.x;
    unsigned m = g_adj[row * NWORD + t];
    int base = t << 5;
    float acc = 0.f;
    while (m) {
        int b = __ffs(m) - 1;
        m &= m - 1;
        acc += __ldg(&y[base + b]);
    }
    #pragma unroll
    for (int o = 16; o; o >>= 1) acc += __shfl_xor_sync(0xffffffffu, acc, o);
    if ((t & 31) == 0) sred[t >> 5] = acc;
    __syncthreads();
    if (t == 0) {
        float v = 0.f;
        #pragma unroll
        for (int i = 0; i < 8; i++) v += sred[i];
        float a = v * g_inv[row];
        if (MODE == 0) {
            out[row] = fmaxf(a + w0[0] + g_yr[row], 0.f);
        } else {
            float o = a * w0[0] + w1[0] + y[row] * w2[0] + g_sc[row];
            out[row] = 1.0f / (1.0f + expf(-o));
        }
    }
}

// ----------------- 8. three fused matvecs -----------------
__global__ void k_matvec3(const float* __restrict__ h,
                          const float* __restrict__ wl, const float* __restrict__ wr,
                          const float* __restrict__ wsc, const float* __restrict__ oscb) {
    int gw   = (blockIdx.x * blockDim.x + threadIdx.x) >> 5;   // one warp per row
    int lane = threadIdx.x & 31;
    if (gw >= NN) return;
    const float* hr = h + (size_t)gw * HDIM;
    float sl = 0.f, sr = 0.f, ss = 0.f;
    #pragma unroll
    for (int u = 0; u < HDIM / 32; u++) {
        int idx = lane + u * 32;
        float v = hr[idx];
        sl += v * __ldg(&wl[idx]);
        sr += v * __ldg(&wr[idx]);
        ss += v * __ldg(&wsc[idx]);
    }
    #pragma unroll
    for (int o = 16; o; o >>= 1) {
        sl += __shfl_xor_sync(0xffffffffu, sl, o);
        sr += __shfl_xor_sync(0xffffffffu, sr, o);
        ss += __shfl_xor_sync(0xffffffffu, ss, o);
    }
    if (lane == 0) {
        g_yl[gw] = sl;
        g_yr[gw] = sr;
        g_sc[gw] = ss + oscb[0];
    }
}

// ========================= launch =========================
extern "C" void kernel_launch(void* const* d_in, const int* in_sizes, int n_in,
                              void* d_out, int out_size) {
    const float* x     = (const float*)d_in[0];
    const float* w_in  = (const float*)d_in[1];
    const float* b_in  = (const float*)d_in[2];
    const float* h1_wl = (const float*)d_in[3];
    const float* h1_bl = (const float*)d_in[4];
    const float* h1_wr = (const float*)d_in[5];
    const float* h2_wl = (const float*)d_in[6];
    const float* h2_bl = (const float*)d_in[7];
    const float* h2_wr = (const float*)d_in[8];
    const float* o1_wl = (const float*)d_in[9];
    const float* o1_bl = (const float*)d_in[10];
    const float* o1_wr = (const float*)d_in[11];
    const float* o2_wl = (const float*)d_in[12];
    const float* o2_bl = (const float*)d_in[13];
    const float* o2_wr = (const float*)d_in[14];
    const float* osc_w = (const float*)d_in[15];
    const float* osc_b = (const float*)d_in[16];
    float* out = (float*)d_out;

    // resolve scratch addresses
    float  *p_h0, *p_h1, *p_h2, *p_agg, *p_yl, *p_o1;
    __half *p_h0f, *p_h1f;
    cudaGetSymbolAddress((void**)&p_h0,  g_h0);
    cudaGetSymbolAddress((void**)&p_h1,  g_h1);
    cudaGetSymbolAddress((void**)&p_h2,  g_h2);
    cudaGetSymbolAddress((void**)&p_h0f, g_h0f);
    cudaGetSymbolAddress((void**)&p_h1f, g_h1f);
    cudaGetSymbolAddress((void**)&p_agg, g_agg);
    cudaGetSymbolAddress((void**)&p_yl,  g_yl);
    cudaGetSymbolAddress((void**)&p_o1,  g_o1v);

    // 1) normalize
    k_normalize<<<NN, DIN>>>(x);
    // 2) similarity matrix, upper-triangle tiles only
    dim3 gs(NTILE, NTILE);
    k_simgemm_sym<<<gs, 256>>>();
    // 3) exact quantile: radix select (pass1 compacts candidates; pass2 reads them only)
    k_init_sel<<<32, 256>>>();
    k_hist<0><<<1040, 256>>>();
    k_scan<<<1, 1024>>>(8192, 19);
    k_hist<1><<<1040, 256>>>();
    k_scan<<<1, 1024>>>(8192, 6);
    k_hist2c<<<512, 256>>>();
    k_scan<<<1, 1024>>>(64, 0);
    // 4) adjacency from upper tiles (direct + bit-transposed mirror), then degrees
    k_adj_tile<<<NUT, 256>>>();
    k_deg<<<NN * 32 / 256, 256>>>();
    // 5) h0 = relu(x @ w_in + b_in)   (+ fp16 copy for aggregation)
    dim3 gd(NN / 128, HDIM / 64);
    k_sage<<<gd, 256>>>(x, w_in, DIN, nullptr, nullptr, 0, b_in, nullptr, p_h0, p_h0f, 1);
    // 6) h1 = relu(agg(h0) @ h1_wl + h1_bl + h0 @ h1_wr)
    k_agg<<<NN, 512>>>(p_h0f, p_agg);
    k_sage<<<gd, 256>>>(p_agg, h1_wl, HDIM, p_h0, h1_wr, HDIM, h1_bl, nullptr, p_h1, p_h1f, 1);
    // 7) h2 = relu(agg(h1) @ h2_wl + h2_bl + h1 @ h2_wr + h0)
    k_agg<<<NN, 512>>>(p_h1f, p_agg);
    k_sage<<<gd, 256>>>(p_agg, h2_wl, HDIM, p_h1, h2_wr, HDIM, h2_bl, p_h0, p_h2, nullptr, 1);
    // 8) output heads: agg(h2)@wl == agg(h2@wl)  (linearity) -> scalar aggregations
    k_matvec3<<<NN * 32 / 256, 256>>>(p_h2, o1_wl, o1_wr, osc_w, osc_b);
    // o1 = relu(agg1(yl) + o1_bl + yr)          (fused epilogue)
    k_agg1f<0><<<NN, 256>>>(p_yl, o1_bl, nullptr, nullptr, p_o1);
    // out = sigmoid(agg1(o1)*o2_wl + o2_bl + o1*o2_wr + sc)   (fused epilogue)
    k_agg1f<1><<<NN, 256>>>(p_o1, o2_wl, o2_bl, o2_wr, out);
}

// round 12
// speedup vs baseline: 1.1685x; 1.1685x over previous
#include <cuda_runtime.h>
#include <cuda_fp16.h>
#include <math.h>

#define NN    8192
#define DIN   128
#define HDIM  256
#define NWORD 256               // 8192/32 mask words per row
#define NTILE 64                // 8192/128 tile grid
#define NUT   2080              // upper-triangle tile count (64*65/2)
#define KRANK 63753420u         // nearest-rank index of 0.95 quantile over N*N values

typedef unsigned long long u64;

// packed f32x2 helpers (sm_103a): 2 independent fp32 FMAs per instruction, bit-identical
#define FMA2(d, a, b)   asm("fma.rn.f32x2 %0, %1, %2, %0;" : "+l"(d) : "l"(a), "l"(b))
#define DUP2(d, s)      asm("mov.b64 %0, {%1, %1};" : "=l"(d) : "f"(s))
#define UNPK(lo, hi, s) asm("mov.b64 {%0, %1}, %2;" : "=f"(lo), "=f"(hi) : "l"(s))

// ----------------- device scratch (static globals; no runtime allocation) -----------------
__device__ float    g_xn  [NN * DIN];          // normalized x            (4 MB)
__device__ float    g_sim [(size_t)NN * NN];   // |xn@xn^T|, UPPER TILES ONLY valid
__device__ unsigned g_adj [NN * NWORD];        // adjacency bitmask       (8 MB)
__device__ float    g_inv [NN];                // 1/deg
__device__ float    g_h0  [NN * HDIM];
__device__ float    g_h1  [NN * HDIM];
__device__ float    g_h2  [NN * HDIM];
__device__ __half   g_h0f [NN * HDIM];         // fp16 copy for aggregation
__device__ __half   g_h1f [NN * HDIM];
__device__ float    g_agg [NN * HDIM];
__device__ float    g_yl  [NN];
__device__ float    g_yr  [NN];
__device__ float    g_sc  [NN];
__device__ float    g_o1v [NN];
__device__ unsigned g_hist[8192];
__device__ unsigned g_key;
__device__ unsigned g_rem;

// decode linear upper-triangle tile index -> (bi, bj), bi <= bj
__device__ __forceinline__ void tile_decode(int tl, int& bi, int& bj) {
    int b = 0, rem = tl;
    while (rem >= NTILE - b) { rem -= NTILE - b; b++; }
    bi = b; bj = b + rem;
}

// ----------------- 1. row-normalize x (clamp norm at 1e-8) -----------------
__global__ void k_normalize(const float* __restrict__ x) {
    int row = blockIdx.x;
    int t   = threadIdx.x;                 // 128 threads = 1 col each
    float v = x[row * DIN + t];
    float s = v * v;
    #pragma unroll
    for (int o = 16; o; o >>= 1) s += __shfl_xor_sync(0xffffffffu, s, o);
    __shared__ float ws[4];
    if ((t & 31) == 0) ws[t >> 5] = s;
    __syncthreads();
    float nrm = fmaxf(sqrtf(ws[0] + ws[1] + ws[2] + ws[3]), 1e-8f);
    g_xn[row * DIN + t] = v / nrm;
}

// ----------------- 2. sim = |xn @ xn^T|, upper-triangle tiles ONLY, FFMA2 inner ---------
__global__ void __launch_bounds__(256, 2) k_simgemm_sym() {
    const int bi = blockIdx.x, bj = blockIdx.y;
    if (bj < bi) return;                       // only upper tiles computed & stored

    __shared__ float As[16][132];
    __shared__ float Bs[16][132];

    const int t  = threadIdx.x;
    const int tx = t & 15, ty = t >> 4;
    const int r0 = bi * 128, c0 = bj * 128;

    u64 acc2[8][4];                            // {acc[i][2j], acc[i][2j+1]} packed pairs
    #pragma unroll
    for (int i = 0; i < 8; i++)
        #pragma unroll
        for (int j = 0; j < 4; j++) acc2[i][j] = 0ull;

    for (int k0 = 0; k0 < DIN; k0 += 16) {
        #pragma unroll
        for (int i = 0; i < 2; i++) {
            int lid = t + i * 256;              // 0..511
            int row = lid >> 2;                 // 0..127
            int q   = lid & 3;
            float4 a = *(const float4*)(g_xn + (size_t)(r0 + row) * DIN + k0 + q * 4);
            As[q*4+0][row] = a.x; As[q*4+1][row] = a.y;
            As[q*4+2][row] = a.z; As[q*4+3][row] = a.w;
            float4 b = *(const float4*)(g_xn + (size_t)(c0 + row) * DIN + k0 + q * 4);
            Bs[q*4+0][row] = b.x; Bs[q*4+1][row] = b.y;
            Bs[q*4+2][row] = b.z; Bs[q*4+3][row] = b.w;
        }
        __syncthreads();
        #pragma unroll
        for (int kk = 0; kk < 16; kk++) {
            float a[8];
            *(float4*)&a[0] = *(const float4*)&As[kk][ty * 4];
            *(float4*)&a[4] = *(const float4*)&As[kk][64 + ty * 4];
            u64 bv[4];
            {
                const u64* bp0 = (const u64*)&Bs[kk][tx * 4];
                const u64* bp1 = (const u64*)&Bs[kk][64 + tx * 4];
                bv[0] = bp0[0]; bv[1] = bp0[1];
                bv[2] = bp1[0]; bv[3] = bp1[1];
            }
            #pragma unroll
            for (int i = 0; i < 8; i++) {
                u64 a2; DUP2(a2, a[i]);
                FMA2(acc2[i][0], a2, bv[0]);
                FMA2(acc2[i][1], a2, bv[1]);
                FMA2(acc2[i][2], a2, bv[2]);
                FMA2(acc2[i][3], a2, bv[3]);
            }
        }
        __syncthreads();
    }
    #pragma unroll
    for (int i = 0; i < 8; i++) {
        int row = r0 + ((i >> 2) << 6) + ty * 4 + (i & 3);
        float* dst = g_sim + (size_t)row * NN + c0;
        float v[8];
        #pragma unroll
        for (int j = 0; j < 4; j++) UNPK(v[2*j], v[2*j+1], acc2[i][j]);
        *(float4*)(dst + tx * 4) =
            make_float4(fabsf(v[0]), fabsf(v[1]), fabsf(v[2]), fabsf(v[3]));
        *(float4*)(dst + 64 + tx * 4) =
            make_float4(fabsf(v[4]), fabsf(v[5]), fabsf(v[6]), fabsf(v[7]));
    }
}

// ----------------- 3. exact k-th order statistic: 3-pass radix select over UPPER tiles --
__global__ void k_init_sel() {
    if (threadIdx.x == 0) { g_key = 0u; g_rem = KRANK; }
    for (int i = threadIdx.x; i < 8192; i += blockDim.x) g_hist[i] = 0u;
}

template <int PASS>
__global__ void k_hist() {
    __shared__ unsigned sh[8192];
    const int nb = (PASS == 2) ? 64 : 8192;
    for (int i = threadIdx.x; i < nb; i += blockDim.x) sh[i] = 0u;
    __syncthreads();
    const unsigned key = g_key;
    const unsigned kp1 = key >> 19;
    const unsigned kp2 = key >> 6;
    const int t = threadIdx.x;
    for (int tl = blockIdx.x; tl < NUT; tl += gridDim.x) {
        int bi, bj; tile_decode(tl, bi, bj);
        const unsigned wgt = (bi == bj) ? 1u : 2u;
        const size_t base = (size_t)bi * 128 * NN + bj * 128;
        #pragma unroll 4
        for (int i = 0; i < 16; i++) {
            int lin = i * 256 + t;
            int r = lin >> 5, c = lin & 31;
            float4 v = __ldg((const float4*)(g_sim + base + (size_t)r * NN) + c);
            float vv[4] = {v.x, v.y, v.z, v.w};
            #pragma unroll
            for (int u = 0; u < 4; u++) {
                unsigned b = __float_as_uint(vv[u]);
                if (PASS == 0)      { atomicAdd(&sh[b >> 19], wgt); }
                else if (PASS == 1) { if ((b >> 19) == kp1) atomicAdd(&sh[(b >> 6) & 8191u], wgt); }
                else                { if ((b >> 6)  == kp2) atomicAdd(&sh[b & 63u], wgt); }
            }
        }
    }
    __syncthreads();
    for (int i = threadIdx.x; i < nb; i += blockDim.x) {
        unsigned c = sh[i];
        if (c) atomicAdd(&g_hist[i], c);
    }
}

// parallel-prefix scan: 1024 threads, shfl warp-scan + 32-word combine
__global__ void __launch_bounds__(1024) k_scan(int nbins, int shift) {
    __shared__ unsigned s[8192];
    __shared__ unsigned wsum[32];
    int t = threadIdx.x;                    // 1024 threads, single block
    for (int i = t; i < nbins; i += 1024) s[i] = g_hist[i];
    __syncthreads();
    int per = (nbins + 1023) / 1024;
    int lo = t * per; if (lo > nbins) lo = nbins;
    int hi = lo + per; if (hi > nbins) hi = nbins;
    unsigned mysum = 0;
    for (int i = lo; i < hi; i++) mysum += s[i];
    // inclusive warp scan
    unsigned inc = mysum;
    #pragma unroll
    for (int o = 1; o < 32; o <<= 1) {
        unsigned v = __shfl_up_sync(0xffffffffu, inc, o);
        if ((t & 31) >= o) inc += v;
    }
    if ((t & 31) == 31) wsum[t >> 5] = inc;
    __syncthreads();
    unsigned wpre = 0;
    #pragma unroll
    for (int i = 0; i < 32; i++) if (i < (t >> 5)) wpre += wsum[i];
    unsigned pre = wpre + inc - mysum;      // exclusive prefix for this thread
    unsigned rem = g_rem;
    __syncthreads();                        // all read g_rem before the winner writes it
    if (mysum > 0 && rem >= pre && rem < pre + mysum) {
        unsigned r = rem - pre;
        for (int i = lo; i < hi; i++) {
            if (r < s[i]) { g_key |= ((unsigned)i) << shift; g_rem = r; break; }
            r -= s[i];
        }
    }
    __syncthreads();
    for (int i = t; i < nbins; i += 1024) g_hist[i] = 0u;  // ready for next pass / replay
}

// ----------------- 4. adjacency from upper tiles: direct + bit-transposed mirror --------
__global__ void __launch_bounds__(256) k_adj_tile() {
    __shared__ unsigned bits[128][4];
    int bi, bj; tile_decode(blockIdx.x, bi, bj);
    const int t = threadIdx.x, lane = t & 31, w = t >> 5;   // 8 warps
    const float eps = __uint_as_float(g_key);
    const int r0 = bi * 128, c0 = bj * 128;
    const int cw0 = c0 >> 5, rw0 = r0 >> 5;

    #pragma unroll
    for (int rr = 0; rr < 16; rr++) {
        int r = w * 16 + rr;
        const float* srow = g_sim + (size_t)(r0 + r) * NN + c0;
        #pragma unroll
        for (int q = 0; q < 4; q++) {
            float v = srow[q * 32 + lane];
            unsigned m = __ballot_sync(0xffffffffu, v >= eps);
            if (lane == 0) {
                g_adj[(r0 + r) * NWORD + cw0 + q] = m;
                bits[r][q] = m;
            }
        }
    }
    if (bi == bj) return;
    __syncthreads();

    const int qr = w >> 1;                  // warps 0..7 -> qr 0..3
    const int chalf = (w & 1) * 64;         // c range [chalf, chalf+64)
    unsigned wa = bits[qr * 32 + lane][(chalf >> 5) + 0];
    unsigned wb = bits[qr * 32 + lane][(chalf >> 5) + 1];
    #pragma unroll
    for (int cc = 0; cc < 32; cc++) {
        unsigned m = __ballot_sync(0xffffffffu, (wa >> cc) & 1u);
        if (lane == 0) g_adj[(c0 + chalf + cc) * NWORD + rw0 + qr] = m;
    }
    #pragma unroll
    for (int cc = 0; cc < 32; cc++) {
        unsigned m = __ballot_sync(0xffffffffu, (wb >> cc) & 1u);
        if (lane == 0) g_adj[(c0 + chalf + 32 + cc) * NWORD + rw0 + qr] = m;
    }
}

// ----------------- 4b. degrees: popc over adjacency rows -----------------
__global__ void k_deg() {
    int row  = (blockIdx.x * blockDim.x + threadIdx.x) >> 5;  // one warp / row
    int lane = threadIdx.x & 31;
    if (row >= NN) return;
    const unsigned* ar = g_adj + row * NWORD;
    int cnt = 0;
    #pragma unroll
    for (int i = 0; i < 8; i++) cnt += __popc(ar[lane + i * 32]);
    #pragma unroll
    for (int o = 16; o; o >>= 1) cnt += __shfl_xor_sync(0xffffffffu, cnt, o);
    if (lane == 0) g_inv[row] = 1.0f / fmaxf((float)cnt, 1.0f);
}

// ----------------- 5. fused dense / SAGE GEMM, FFMA2 inner ------------------------------
__global__ void __launch_bounds__(256) k_sage(
    const float* __restrict__ A1, const float* __restrict__ W1, int K1,
    const float* __restrict__ A2, const float* __restrict__ W2, int K2,
    const float* __restrict__ bias, const float* __restrict__ res,
    float* __restrict__ out, __half* __restrict__ out16, int relu)
{
    __shared__ float As[16][132];
    __shared__ float Bs[16][68];
    const int t  = threadIdx.x;
    const int tx = t & 15, ty = t >> 4;
    const int r0 = blockIdx.x * 128, c0 = blockIdx.y * 64;

    u64 acc2[8][2];
    #pragma unroll
    for (int i = 0; i < 8; i++) { acc2[i][0] = 0ull; acc2[i][1] = 0ull; }

    const float* Ap = A1; const float* Wp = W1; int K = K1;
    for (int phase = 0; phase < 2; phase++) {
        if (phase == 1) {
            if (A2 == nullptr) break;
            Ap = A2; Wp = W2; K = K2;
        }
        for (int k0 = 0; k0 < K; k0 += 16) {
            #pragma unroll
            for (int i = 0; i < 2; i++) {
                int lid = t + i * 256;
                int row = lid >> 2;             // 0..127
                int q   = lid & 3;
                float4 a = *(const float4*)(Ap + (size_t)(r0 + row) * K + k0 + q * 4);
                As[q*4+0][row] = a.x; As[q*4+1][row] = a.y;
                As[q*4+2][row] = a.z; As[q*4+3][row] = a.w;
            }
            {
                int kk = t >> 4, n4 = (t & 15) * 4;
                float4 b = *(const float4*)(Wp + (size_t)(k0 + kk) * HDIM + c0 + n4);
                Bs[kk][n4+0] = b.x; Bs[kk][n4+1] = b.y;
                Bs[kk][n4+2] = b.z; Bs[kk][n4+3] = b.w;
            }
            __syncthreads();
            #pragma unroll
            for (int kk = 0; kk < 16; kk++) {
                float a[8];
                *(float4*)&a[0] = *(const float4*)&As[kk][ty * 4];
                *(float4*)&a[4] = *(const float4*)&As[kk][64 + ty * 4];
                u64 bv[2];
                {
                    const u64* bp = (const u64*)&Bs[kk][tx * 4];
                    bv[0] = bp[0]; bv[1] = bp[1];
                }
                #pragma unroll
                for (int i = 0; i < 8; i++) {
                    u64 a2; DUP2(a2, a[i]);
                    FMA2(acc2[i][0], a2, bv[0]);
                    FMA2(acc2[i][1], a2, bv[1]);
                }
            }
            __syncthreads();
        }
    }
    float bvv[4];
    *(float4*)bvv = *(const float4*)(bias + c0 + tx * 4);
    #pragma unroll
    for (int i = 0; i < 8; i++) {
        int row = r0 + ((i >> 2) << 6) + ty * 4 + (i & 3);
        float v[4];
        UNPK(v[0], v[1], acc2[i][0]);
        UNPK(v[2], v[3], acc2[i][1]);
        #pragma unroll
        for (int j = 0; j < 4; j++) v[j] += bvv[j];
        if (res) {
            float4 rr = *(const float4*)(res + (size_t)row * HDIM + c0 + tx * 4);
            v[0] += rr.x; v[1] += rr.y; v[2] += rr.z; v[3] += rr.w;
        }
        if (relu) {
            #pragma unroll
            for (int j = 0; j < 4; j++) v[j] = fmaxf(v[j], 0.f);
        }
        *(float4*)(out + (size_t)row * HDIM + c0 + tx * 4) = make_float4(v[0], v[1], v[2], v[3]);
        if (out16) {
            __half2 h01 = __floats2half2_rn(v[0], v[1]);
            __half2 h23 = __floats2half2_rn(v[2], v[3]);
            uint2 pk;
            pk.x = *(unsigned*)&h01;
            pk.y = *(unsigned*)&h23;
            *(uint2*)(out16 + (size_t)row * HDIM + c0 + tx * 4) = pk;
        }
    }
}

// ----------------- 6. mean aggregation, width 256, fp16 input, fp32 accumulate ----------
// (R6/R9 proven version: per-row, 4 groups x 64 threads, uint2 loads)
__global__ void __launch_bounds__(256) k_agg(const __half* __restrict__ h, float* __restrict__ out) {
    __shared__ unsigned sm[NWORD];
    __shared__ float red[4][HDIM];
    int row = blockIdx.x;
    int t   = threadIdx.x;
    int g   = t >> 6;                       // group 0..3 (its own 64 mask words)
    int c4  = t & 63;                       // this thread's 4-column slot
    sm[t] = g_adj[row * NWORD + t];
    __syncthreads();
    float4 acc = make_float4(0.f, 0.f, 0.f, 0.f);
    for (int w = g * 64; w < g * 64 + 64; w++) {
        unsigned m = sm[w];
        int base = w << 5;
        while (m) {
            int b0 = __ffs(m) - 1; m &= m - 1;
            uint2 r0 = __ldg((const uint2*)(h + ((size_t)(base + b0) << 8)) + c4);
            if (m) {
                int b1 = __ffs(m) - 1; m &= m - 1;
                uint2 r1 = __ldg((const uint2*)(h + ((size_t)(base + b1) << 8)) + c4);
                float2 a0 = __half22float2(*(__half2*)&r0.x);
                float2 a1 = __half22float2(*(__half2*)&r0.y);
                float2 b0v = __half22float2(*(__half2*)&r1.x);
                float2 b1v = __half22float2(*(__half2*)&r1.y);
                acc.x += a0.x + b0v.x; acc.y += a0.y + b0v.y;
                acc.z += a1.x + b1v.x; acc.w += a1.y + b1v.y;
            } else {
                float2 a0 = __half22float2(*(__half2*)&r0.x);
                float2 a1 = __half22float2(*(__half2*)&r0.y);
                acc.x += a0.x; acc.y += a0.y;
                acc.z += a1.x; acc.w += a1.y;
            }
        }
    }
    ((float4*)red[g])[c4] = acc;
    __syncthreads();
    if (t < 64) {
        float4 a0 = ((float4*)red[0])[t];
        float4 a1 = ((float4*)red[1])[t];
        float4 a2 = ((float4*)red[2])[t];
        float4 a3 = ((float4*)red[3])[t];
        float inv = g_inv[row];
        float4 r;
        r.x = (a0.x + a1.x + a2.x + a3.x) * inv;
        r.y = (a0.y + a1.y + a2.y + a3.y) * inv;
        r.z = (a0.z + a1.z + a2.z + a3.z) * inv;
        r.w = (a0.w + a1.w + a2.w + a3.w) * inv;
        ((float4*)(out + ((size_t)row << 8)))[t] = r;
    }
}

// ----------------- 7. width-1 aggregation with fused epilogues -----------------
// mode 0: out[row] = relu(agg1(y)[row] + w0 + g_yr[row])
// mode 1: out[row] = sigmoid(agg1(y)[row]*w0 + w1 + y[row]*w2 + g_sc[row])
template <int MODE>
__global__ void __launch_bounds__(256) k_agg1f(const float* __restrict__ y,
                                               const float* __restrict__ w0,
                                               const float* __restrict__ w1,
                                               const float* __restrict__ w2,
                                               float* __restrict__ out) {
    __shared__ float sred[8];
    int row = blockIdx.x, t = threadIdx.x;
    unsigned m = g_adj[row * NWORD + t];
    int base = t << 5;
    float acc = 0.f;
    while (m) {
        int b = __ffs(m) - 1;
        m &= m - 1;
        acc += __ldg(&y[base + b]);
    }
    #pragma unroll
    for (int o = 16; o; o >>= 1) acc += __shfl_xor_sync(0xffffffffu, acc, o);
    if ((t & 31) == 0) sred[t >> 5] = acc;
    __syncthreads();
    if (t == 0) {
        float v = 0.f;
        #pragma unroll
        for (int i = 0; i < 8; i++) v += sred[i];
        float a = v * g_inv[row];
        if (MODE == 0) {
            out[row] = fmaxf(a + w0[0] + g_yr[row], 0.f);
        } else {
            float o = a * w0[0] + w1[0] + y[row] * w2[0] + g_sc[row];
            out[row] = 1.0f / (1.0f + expf(-o));
        }
    }
}

// ----------------- 8. three fused matvecs -----------------
__global__ void k_matvec3(const float* __restrict__ h,
                          const float* __restrict__ wl, const float* __restrict__ wr,
                          const float* __restrict__ wsc, const float* __restrict__ oscb) {
    int gw   = (blockIdx.x * blockDim.x + threadIdx.x) >> 5;   // one warp per row
    int lane = threadIdx.x & 31;
    if (gw >= NN) return;
    const float* hr = h + (size_t)gw * HDIM;
    float sl = 0.f, sr = 0.f, ss = 0.f;
    #pragma unroll
    for (int u = 0; u < HDIM / 32; u++) {
        int idx = lane + u * 32;
        float v = hr[idx];
        sl += v * __ldg(&wl[idx]);
        sr += v * __ldg(&wr[idx]);
        ss += v * __ldg(&wsc[idx]);
    }
    #pragma unroll
    for (int o = 16; o; o >>= 1) {
        sl += __shfl_xor_sync(0xffffffffu, sl, o);
        sr += __shfl_xor_sync(0xffffffffu, sr, o);
        ss += __shfl_xor_sync(0xffffffffu, ss, o);
    }
    if (lane == 0) {
        g_yl[gw] = sl;
        g_yr[gw] = sr;
        g_sc[gw] = ss + oscb[0];
    }
}

// ========================= launch =========================
extern "C" void kernel_launch(void* const* d_in, const int* in_sizes, int n_in,
                              void* d_out, int out_size) {
    const float* x     = (const float*)d_in[0];
    const float* w_in  = (const float*)d_in[1];
    const float* b_in  = (const float*)d_in[2];
    const float* h1_wl = (const float*)d_in[3];
    const float* h1_bl = (const float*)d_in[4];
    const float* h1_wr = (const float*)d_in[5];
    const float* h2_wl = (const float*)d_in[6];
    const float* h2_bl = (const float*)d_in[7];
    const float* h2_wr = (const float*)d_in[8];
    const float* o1_wl = (const float*)d_in[9];
    const float* o1_bl = (const float*)d_in[10];
    const float* o1_wr = (const float*)d_in[11];
    const float* o2_wl = (const float*)d_in[12];
    const float* o2_bl = (const float*)d_in[13];
    const float* o2_wr = (const float*)d_in[14];
    const float* osc_w = (const float*)d_in[15];
    const float* osc_b = (const float*)d_in[16];
    float* out = (float*)d_out;

    // resolve scratch addresses
    float  *p_h0, *p_h1, *p_h2, *p_agg, *p_yl, *p_o1;
    __half *p_h0f, *p_h1f;
    cudaGetSymbolAddress((void**)&p_h0,  g_h0);
    cudaGetSymbolAddress((void**)&p_h1,  g_h1);
    cudaGetSymbolAddress((void**)&p_h2,  g_h2);
    cudaGetSymbolAddress((void**)&p_h0f, g_h0f);
    cudaGetSymbolAddress((void**)&p_h1f, g_h1f);
    cudaGetSymbolAddress((void**)&p_agg, g_agg);
    cudaGetSymbolAddress((void**)&p_yl,  g_yl);
    cudaGetSymbolAddress((void**)&p_o1,  g_o1v);

    // 1) normalize
    k_normalize<<<NN, DIN>>>(x);
    // 2) similarity matrix, upper-triangle tiles only
    dim3 gs(NTILE, NTILE);
    k_simgemm_sym<<<gs, 256>>>();
    // 3) exact quantile: 3-pass radix select over upper tiles (weight 2 off-diag)
    k_init_sel<<<1, 256>>>();
    k_hist<0><<<1040, 256>>>();
    k_scan<<<1, 1024>>>(8192, 19);
    k_hist<1><<<1040, 256>>>();
    k_scan<<<1, 1024>>>(8192, 6);
    k_hist<2><<<1040, 256>>>();
    k_scan<<<1, 1024>>>(64, 0);
    // 4) adjacency from upper tiles (direct + bit-transposed mirror), then degrees
    k_adj_tile<<<NUT, 256>>>();
    k_deg<<<NN * 32 / 256, 256>>>();
    // 5) h0 = relu(x @ w_in + b_in)   (+ fp16 copy for aggregation)
    dim3 gd(NN / 128, HDIM / 64);
    k_sage<<<gd, 256>>>(x, w_in, DIN, nullptr, nullptr, 0, b_in, nullptr, p_h0, p_h0f, 1);
    // 6) h1 = relu(agg(h0) @ h1_wl + h1_bl + h0 @ h1_wr)
    k_agg<<<NN, 256>>>(p_h0f, p_agg);
    k_sage<<<gd, 256>>>(p_agg, h1_wl, HDIM, p_h0, h1_wr, HDIM, h1_bl, nullptr, p_h1, p_h1f, 1);
    // 7) h2 = relu(agg(h1) @ h2_wl + h2_bl + h1 @ h2_wr + h0)
    k_agg<<<NN, 256>>>(p_h1f, p_agg);
    k_sage<<<gd, 256>>>(p_agg, h2_wl, HDIM, p_h1, h2_wr, HDIM, h2_bl, p_h0, p_h2, nullptr, 1);
    // 8) output heads: agg(h2)@wl == agg(h2@wl)  (linearity) -> scalar aggregations
    k_matvec3<<<NN * 32 / 256, 256>>>(p_h2, o1_wl, o1_wr, osc_w, osc_b);
    // o1 = relu(agg1(yl) + o1_bl + yr)          (fused epilogue)
    k_agg1f<0><<<NN, 256>>>(p_yl, o1_bl, nullptr, nullptr, p_o1);
    // out = sigmoid(agg1(o1)*o2_wl + o2_bl + o1*o2_wr + sc)   (fused epilogue)
    k_agg1f<1><<<NN, 256>>>(p_o1, o2_wl, o2_bl, o2_wr, out);
}

// round 13
// speedup vs baseline: 1.1827x; 1.0122x over previous
#include <cuda_runtime.h>
#include <cuda_fp16.h>
#include <math.h>

#define NN    8192
#define DIN   128
#define HDIM  256
#define NWORD 256               // 8192/32 mask words per row
#define NTILE 64                // 8192/128 tile grid
#define NUT   2080              // upper-triangle tile count (64*65/2)
#define KRANK 63753420u         // nearest-rank index of 0.95 quantile over N*N values
#define CAND_CAP (1u << 24)     // 16M candidate slots (64 MB)

typedef unsigned long long u64;

// packed f32x2 helpers (sm_103a): 2 independent fp32 FMAs per instruction, bit-identical
#define FMA2(d, a, b)   asm("fma.rn.f32x2 %0, %1, %2, %0;" : "+l"(d) : "l"(a), "l"(b))
#define DUP2(d, s)      asm("mov.b64 %0, {%1, %1};" : "=l"(d) : "f"(s))
#define UNPK(lo, hi, s) asm("mov.b64 {%0, %1}, %2;" : "=f"(lo), "=f"(hi) : "l"(s))

// ----------------- device scratch (static globals; no runtime allocation) -----------------
__device__ float    g_xn  [NN * DIN];          // normalized x            (4 MB)
__device__ float    g_sim [(size_t)NN * NN];   // |xn@xn^T|, UPPER TILES ONLY valid
__device__ unsigned g_adj [NN * NWORD];        // adjacency bitmask       (8 MB)
__device__ float    g_inv [NN];                // 1/deg
__device__ float    g_h0  [NN * HDIM];
__device__ float    g_h1  [NN * HDIM];
__device__ float    g_h2  [NN * HDIM];
__device__ __half   g_h0f [NN * HDIM];         // fp16 copy for aggregation
__device__ __half   g_h1f [NN * HDIM];
__device__ float    g_agg [NN * HDIM];
__device__ float    g_yl  [NN];
__device__ float    g_yr  [NN];
__device__ float    g_sc  [NN];
__device__ float    g_o1v [NN];
__device__ unsigned g_hist[8192];
__device__ unsigned g_cand[CAND_CAP];          // compacted pass-1 candidates
__device__ unsigned g_cnt;
__device__ unsigned g_key;
__device__ unsigned g_rem;

// decode linear upper-triangle tile index -> (bi, bj), bi <= bj
__device__ __forceinline__ void tile_decode(int tl, int& bi, int& bj) {
    int b = 0, rem = tl;
    while (rem >= NTILE - b) { rem -= NTILE - b; b++; }
    bi = b; bj = b + rem;
}

// ----------------- 1. row-normalize x (clamp norm at 1e-8) -----------------
__global__ void k_normalize(const float* __restrict__ x) {
    int row = blockIdx.x;
    int t   = threadIdx.x;                 // 128 threads = 1 col each
    float v = x[row * DIN + t];
    float s = v * v;
    #pragma unroll
    for (int o = 16; o; o >>= 1) s += __shfl_xor_sync(0xffffffffu, s, o);
    __shared__ float ws[4];
    if ((t & 31) == 0) ws[t >> 5] = s;
    __syncthreads();
    float nrm = fmaxf(sqrtf(ws[0] + ws[1] + ws[2] + ws[3]), 1e-8f);
    g_xn[row * DIN + t] = v / nrm;
}

// ----------------- 2. sim = |xn @ xn^T|, upper-triangle tiles ONLY, FFMA2 inner ---------
__global__ void __launch_bounds__(256, 2) k_simgemm_sym() {
    const int bi = blockIdx.x, bj = blockIdx.y;
    if (bj < bi) return;                       // only upper tiles computed & stored

    __shared__ float As[16][132];
    __shared__ float Bs[16][132];

    const int t  = threadIdx.x;
    const int tx = t & 15, ty = t >> 4;
    const int r0 = bi * 128, c0 = bj * 128;

    u64 acc2[8][4];                            // {acc[i][2j], acc[i][2j+1]} packed pairs
    #pragma unroll
    for (int i = 0; i < 8; i++)
        #pragma unroll
        for (int j = 0; j < 4; j++) acc2[i][j] = 0ull;

    for (int k0 = 0; k0 < DIN; k0 += 16) {
        #pragma unroll
        for (int i = 0; i < 2; i++) {
            int lid = t + i * 256;              // 0..511
            int row = lid >> 2;                 // 0..127
            int q   = lid & 3;
            float4 a = *(const float4*)(g_xn + (size_t)(r0 + row) * DIN + k0 + q * 4);
            As[q*4+0][row] = a.x; As[q*4+1][row] = a.y;
            As[q*4+2][row] = a.z; As[q*4+3][row] = a.w;
            float4 b = *(const float4*)(g_xn + (size_t)(c0 + row) * DIN + k0 + q * 4);
            Bs[q*4+0][row] = b.x; Bs[q*4+1][row] = b.y;
            Bs[q*4+2][row] = b.z; Bs[q*4+3][row] = b.w;
        }
        __syncthreads();
        #pragma unroll
        for (int kk = 0; kk < 16; kk++) {
            float a[8];
            *(float4*)&a[0] = *(const float4*)&As[kk][ty * 4];
            *(float4*)&a[4] = *(const float4*)&As[kk][64 + ty * 4];
            u64 bv[4];
            {
                const u64* bp0 = (const u64*)&Bs[kk][tx * 4];
                const u64* bp1 = (const u64*)&Bs[kk][64 + tx * 4];
                bv[0] = bp0[0]; bv[1] = bp0[1];
                bv[2] = bp1[0]; bv[3] = bp1[1];
            }
            #pragma unroll
            for (int i = 0; i < 8; i++) {
                u64 a2; DUP2(a2, a[i]);
                FMA2(acc2[i][0], a2, bv[0]);
                FMA2(acc2[i][1], a2, bv[1]);
                FMA2(acc2[i][2], a2, bv[2]);
                FMA2(acc2[i][3], a2, bv[3]);
            }
        }
        __syncthreads();
    }
    #pragma unroll
    for (int i = 0; i < 8; i++) {
        int row = r0 + ((i >> 2) << 6) + ty * 4 + (i & 3);
        float* dst = g_sim + (size_t)row * NN + c0;
        float v[8];
        #pragma unroll
        for (int j = 0; j < 4; j++) UNPK(v[2*j], v[2*j+1], acc2[i][j]);
        *(float4*)(dst + tx * 4) =
            make_float4(fabsf(v[0]), fabsf(v[1]), fabsf(v[2]), fabsf(v[3]));
        *(float4*)(dst + 64 + tx * 4) =
            make_float4(fabsf(v[4]), fabsf(v[5]), fabsf(v[6]), fabsf(v[7]));
    }
}

// ----------------- 3. exact k-th order statistic: radix select over UPPER tiles ---------
// Pass 0: bits[31:19]. Pass 1: bits[18:6] + block-staged candidate compaction.
// Pass 2: bits[5:0] over compacted candidates (fallback: full scan if overflow).
__global__ void k_init_sel() {
    if (threadIdx.x == 0) { g_key = 0u; g_rem = KRANK; g_cnt = 0u; }
    for (int i = threadIdx.x; i < 8192; i += blockDim.x) g_hist[i] = 0u;
}

template <int PASS>
__global__ void k_hist() {
    __shared__ unsigned sh[8192];
    __shared__ unsigned buf[(PASS == 1) ? 4096 : 1];
    __shared__ unsigned bcnt, gbase;
    for (int i = threadIdx.x; i < 8192; i += blockDim.x) sh[i] = 0u;
    if (threadIdx.x == 0) bcnt = 0u;
    __syncthreads();
    const unsigned key = g_key;
    const unsigned kp1 = key >> 19;
    const int t = threadIdx.x;
    for (int tl = blockIdx.x; tl < NUT; tl += gridDim.x) {
        int bi, bj; tile_decode(tl, bi, bj);
        const unsigned wgt = (bi == bj) ? 1u : 2u;
        const size_t base = (size_t)bi * 128 * NN + bj * 128;
        #pragma unroll 4
        for (int i = 0; i < 16; i++) {
            int lin = i * 256 + t;
            int r = lin >> 5, c = lin & 31;
            float4 v = __ldg((const float4*)(g_sim + base + (size_t)r * NN) + c);
            float vv[4] = {v.x, v.y, v.z, v.w};
            #pragma unroll
            for (int u = 0; u < 4; u++) {
                unsigned b = __float_as_uint(vv[u]);
                if (PASS == 0) {
                    atomicAdd(&sh[b >> 19], wgt);
                } else {
                    if ((b >> 19) == kp1) {
                        atomicAdd(&sh[(b >> 6) & 8191u], wgt);
                        unsigned slot = atomicAdd(&bcnt, wgt);   // smem atomic, rare
                        buf[slot] = b;
                        if (wgt == 2u) buf[slot + 1] = b;
                    }
                }
            }
            if (PASS == 1) {
                __syncthreads();
                if (bcnt > 2048u) {              // flush: ONE global atomic per ~2K cands
                    if (t == 0) gbase = atomicAdd(&g_cnt, bcnt);
                    __syncthreads();
                    unsigned n = bcnt, gb = gbase;
                    for (unsigned j = t; j < n; j += 256)
                        if (gb + j < CAND_CAP) g_cand[gb + j] = buf[j];
                    __syncthreads();
                    if (t == 0) bcnt = 0u;
                    __syncthreads();
                }
            }
        }
    }
    if (PASS == 1) {                              // final flush
        __syncthreads();
        if (bcnt > 0u) {
            if (t == 0) gbase = atomicAdd(&g_cnt, bcnt);
            __syncthreads();
            unsigned n = bcnt, gb = gbase;
            for (unsigned j = t; j < n; j += 256)
                if (gb + j < CAND_CAP) g_cand[gb + j] = buf[j];
        }
    }
    __syncthreads();
    for (int i = threadIdx.x; i < 8192; i += blockDim.x) {
        unsigned c = sh[i];
        if (c) atomicAdd(&g_hist[i], c);
    }
}

// pass 2: histogram bits[5:0] over compacted candidates; full-scan fallback on overflow
__global__ void k_hist2c() {
    __shared__ unsigned sh[64];
    if (threadIdx.x < 64) sh[threadIdx.x] = 0u;
    __syncthreads();
    const unsigned key = g_key;
    const unsigned kp2 = key >> 6;
    const unsigned n = g_cnt;
    if (n <= CAND_CAP) {
        // compacted path: candidates are weight-expanded, count each once
        for (unsigned i = blockIdx.x * blockDim.x + threadIdx.x; i < n;
             i += gridDim.x * blockDim.x) {
            unsigned b = g_cand[i];
            if ((b >> 6) == kp2) atomicAdd(&sh[b & 63u], 1u);
        }
    } else {
        // fallback: full tile scan (bit-exact original pass 2)
        const int t = threadIdx.x;
        for (int tl = blockIdx.x; tl < NUT; tl += (int)gridDim.x) {
            int bi, bj; tile_decode(tl, bi, bj);
            const unsigned wgt = (bi == bj) ? 1u : 2u;
            const size_t base = (size_t)bi * 128 * NN + bj * 128;
            #pragma unroll 4
            for (int i = 0; i < 16; i++) {
                int lin = i * 256 + t;
                int r = lin >> 5, c = lin & 31;
                float4 v = __ldg((const float4*)(g_sim + base + (size_t)r * NN) + c);
                float vv[4] = {v.x, v.y, v.z, v.w};
                #pragma unroll
                for (int u = 0; u < 4; u++) {
                    unsigned b = __float_as_uint(vv[u]);
                    if ((b >> 6) == kp2) atomicAdd(&sh[b & 63u], wgt);
                }
            }
        }
    }
    __syncthreads();
    if (threadIdx.x < 64) {
        unsigned c = sh[threadIdx.x];
        if (c) atomicAdd(&g_hist[threadIdx.x], c);
    }
}

// parallel-prefix scan: 1024 threads, shfl warp-scan + 32-word combine
__global__ void __launch_bounds__(1024) k_scan(int nbins, int shift) {
    __shared__ unsigned s[8192];
    __shared__ unsigned wsum[32];
    int t = threadIdx.x;                    // 1024 threads, single block
    for (int i = t; i < nbins; i += 1024) s[i] = g_hist[i];
    __syncthreads();
    int per = (nbins + 1023) / 1024;
    int lo = t * per; if (lo > nbins) lo = nbins;
    int hi = lo + per; if (hi > nbins) hi = nbins;
    unsigned mysum = 0;
    for (int i = lo; i < hi; i++) mysum += s[i];
    // inclusive warp scan
    unsigned inc = mysum;
    #pragma unroll
    for (int o = 1; o < 32; o <<= 1) {
        unsigned v = __shfl_up_sync(0xffffffffu, inc, o);
        if ((t & 31) >= o) inc += v;
    }
    if ((t & 31) == 31) wsum[t >> 5] = inc;
    __syncthreads();
    unsigned wpre = 0;
    #pragma unroll
    for (int i = 0; i < 32; i++) if (i < (t >> 5)) wpre += wsum[i];
    unsigned pre = wpre + inc - mysum;      // exclusive prefix for this thread
    unsigned rem = g_rem;
    __syncthreads();                        // all read g_rem before the winner writes it
    if (mysum > 0 && rem >= pre && rem < pre + mysum) {
        unsigned r = rem - pre;
        for (int i = lo; i < hi; i++) {
            if (r < s[i]) { g_key |= ((unsigned)i) << shift; g_rem = r; break; }
            r -= s[i];
        }
    }
    __syncthreads();
    for (int i = t; i < nbins; i += 1024) g_hist[i] = 0u;  // ready for next pass / replay
}

// ----------------- 4. adjacency from upper tiles: direct + bit-transposed mirror --------
__global__ void __launch_bounds__(256) k_adj_tile() {
    __shared__ unsigned bits[128][4];
    int bi, bj; tile_decode(blockIdx.x, bi, bj);
    const int t = threadIdx.x, lane = t & 31, w = t >> 5;   // 8 warps
    const float eps = __uint_as_float(g_key);
    const int r0 = bi * 128, c0 = bj * 128;
    const int cw0 = c0 >> 5, rw0 = r0 >> 5;

    #pragma unroll
    for (int rr = 0; rr < 16; rr++) {
        int r = w * 16 + rr;
        const float* srow = g_sim + (size_t)(r0 + r) * NN + c0;
        #pragma unroll
        for (int q = 0; q < 4; q++) {
            float v = srow[q * 32 + lane];
            unsigned m = __ballot_sync(0xffffffffu, v >= eps);
            if (lane == 0) {
                g_adj[(r0 + r) * NWORD + cw0 + q] = m;
                bits[r][q] = m;
            }
        }
    }
    if (bi == bj) return;
    __syncthreads();

    const int qr = w >> 1;                  // warps 0..7 -> qr 0..3
    const int chalf = (w & 1) * 64;         // c range [chalf, chalf+64)
    unsigned wa = bits[qr * 32 + lane][(chalf >> 5) + 0];
    unsigned wb = bits[qr * 32 + lane][(chalf >> 5) + 1];
    #pragma unroll
    for (int cc = 0; cc < 32; cc++) {
        unsigned m = __ballot_sync(0xffffffffu, (wa >> cc) & 1u);
        if (lane == 0) g_adj[(c0 + chalf + cc) * NWORD + rw0 + qr] = m;
    }
    #pragma unroll
    for (int cc = 0; cc < 32; cc++) {
        unsigned m = __ballot_sync(0xffffffffu, (wb >> cc) & 1u);
        if (lane == 0) g_adj[(c0 + chalf + 32 + cc) * NWORD + rw0 + qr] = m;
    }
}

// ----------------- 4b. degrees: popc over adjacency rows -----------------
__global__ void k_deg() {
    int row  = (blockIdx.x * blockDim.x + threadIdx.x) >> 5;  // one warp / row
    int lane = threadIdx.x & 31;
    if (row >= NN) return;
    const unsigned* ar = g_adj + row * NWORD;
    int cnt = 0;
    #pragma unroll
    for (int i = 0; i < 8; i++) cnt += __popc(ar[lane + i * 32]);
    #pragma unroll
    for (int o = 16; o; o >>= 1) cnt += __shfl_xor_sync(0xffffffffu, cnt, o);
    if (lane == 0) g_inv[row] = 1.0f / fmaxf((float)cnt, 1.0f);
}

// ----------------- 5. fused dense / SAGE GEMM, FFMA2 inner ------------------------------
__global__ void __launch_bounds__(256) k_sage(
    const float* __restrict__ A1, const float* __restrict__ W1, int K1,
    const float* __restrict__ A2, const float* __restrict__ W2, int K2,
    const float* __restrict__ bias, const float* __restrict__ res,
    float* __restrict__ out, __half* __restrict__ out16, int relu)
{
    __shared__ float As[16][132];
    __shared__ float Bs[16][68];
    const int t  = threadIdx.x;
    const int tx = t & 15, ty = t >> 4;
    const int r0 = blockIdx.x * 128, c0 = blockIdx.y * 64;

    u64 acc2[8][2];
    #pragma unroll
    for (int i = 0; i < 8; i++) { acc2[i][0] = 0ull; acc2[i][1] = 0ull; }

    const float* Ap = A1; const float* Wp = W1; int K = K1;
    for (int phase = 0; phase < 2; phase++) {
        if (phase == 1) {
            if (A2 == nullptr) break;
            Ap = A2; Wp = W2; K = K2;
        }
        for (int k0 = 0; k0 < K; k0 += 16) {
            #pragma unroll
            for (int i = 0; i < 2; i++) {
                int lid = t + i * 256;
                int row = lid >> 2;             // 0..127
                int q   = lid & 3;
                float4 a = *(const float4*)(Ap + (size_t)(r0 + row) * K + k0 + q * 4);
                As[q*4+0][row] = a.x; As[q*4+1][row] = a.y;
                As[q*4+2][row] = a.z; As[q*4+3][row] = a.w;
            }
            {
                int kk = t >> 4, n4 = (t & 15) * 4;
                float4 b = *(const float4*)(Wp + (size_t)(k0 + kk) * HDIM + c0 + n4);
                Bs[kk][n4+0] = b.x; Bs[kk][n4+1] = b.y;
                Bs[kk][n4+2] = b.z; Bs[kk][n4+3] = b.w;
            }
            __syncthreads();
            #pragma unroll
            for (int kk = 0; kk < 16; kk++) {
                float a[8];
                *(float4*)&a[0] = *(const float4*)&As[kk][ty * 4];
                *(float4*)&a[4] = *(const float4*)&As[kk][64 + ty * 4];
                u64 bv[2];
                {
                    const u64* bp = (const u64*)&Bs[kk][tx * 4];
                    bv[0] = bp[0]; bv[1] = bp[1];
                }
                #pragma unroll
                for (int i = 0; i < 8; i++) {
                    u64 a2; DUP2(a2, a[i]);
                    FMA2(acc2[i][0], a2, bv[0]);
                    FMA2(acc2[i][1], a2, bv[1]);
                }
            }
            __syncthreads();
        }
    }
    float bvv[4];
    *(float4*)bvv = *(const float4*)(bias + c0 + tx * 4);
    #pragma unroll
    for (int i = 0; i < 8; i++) {
        int row = r0 + ((i >> 2) << 6) + ty * 4 + (i & 3);
        float v[4];
        UNPK(v[0], v[1], acc2[i][0]);
        UNPK(v[2], v[3], acc2[i][1]);
        #pragma unroll
        for (int j = 0; j < 4; j++) v[j] += bvv[j];
        if (res) {
            float4 rr = *(const float4*)(res + (size_t)row * HDIM + c0 + tx * 4);
            v[0] += rr.x; v[1] += rr.y; v[2] += rr.z; v[3] += rr.w;
        }
        if (relu) {
            #pragma unroll
            for (int j = 0; j < 4; j++) v[j] = fmaxf(v[j], 0.f);
        }
        *(float4*)(out + (size_t)row * HDIM + c0 + tx * 4) = make_float4(v[0], v[1], v[2], v[3]);
        if (out16) {
            __half2 h01 = __floats2half2_rn(v[0], v[1]);
            __half2 h23 = __floats2half2_rn(v[2], v[3]);
            uint2 pk;
            pk.x = *(unsigned*)&h01;
            pk.y = *(unsigned*)&h23;
            *(uint2*)(out16 + (size_t)row * HDIM + c0 + tx * 4) = pk;
        }
    }
}

// ----------------- 6. mean aggregation, width 256, fp16 input, fp32 accumulate ----------
// (R6/R9 proven version: per-row, 4 groups x 64 threads, uint2 loads)
__global__ void __launch_bounds__(256) k_agg(const __half* __restrict__ h, float* __restrict__ out) {
    __shared__ unsigned sm[NWORD];
    __shared__ float red[4][HDIM];
    int row = blockIdx.x;
    int t   = threadIdx.x;
    int g   = t >> 6;                       // group 0..3 (its own 64 mask words)
    int c4  = t & 63;                       // this thread's 4-column slot
    sm[t] = g_adj[row * NWORD + t];
    __syncthreads();
    float4 acc = make_float4(0.f, 0.f, 0.f, 0.f);
    for (int w = g * 64; w < g * 64 + 64; w++) {
        unsigned m = sm[w];
        int base = w << 5;
        while (m) {
            int b0 = __ffs(m) - 1; m &= m - 1;
            uint2 r0 = __ldg((const uint2*)(h + ((size_t)(base + b0) << 8)) + c4);
            if (m) {
                int b1 = __ffs(m) - 1; m &= m - 1;
                uint2 r1 = __ldg((const uint2*)(h + ((size_t)(base + b1) << 8)) + c4);
                float2 a0 = __half22float2(*(__half2*)&r0.x);
                float2 a1 = __half22float2(*(__half2*)&r0.y);
                float2 b0v = __half22float2(*(__half2*)&r1.x);
                float2 b1v = __half22float2(*(__half2*)&r1.y);
                acc.x += a0.x + b0v.x; acc.y += a0.y + b0v.y;
                acc.z += a1.x + b1v.x; acc.w += a1.y + b1v.y;
            } else {
                float2 a0 = __half22float2(*(__half2*)&r0.x);
                float2 a1 = __half22float2(*(__half2*)&r0.y);
                acc.x += a0.x; acc.y += a0.y;
                acc.z += a1.x; acc.w += a1.y;
            }
        }
    }
    ((float4*)red[g])[c4] = acc;
    __syncthreads();
    if (t < 64) {
        float4 a0 = ((float4*)red[0])[t];
        float4 a1 = ((float4*)red[1])[t];
        float4 a2 = ((float4*)red[2])[t];
        float4 a3 = ((float4*)red[3])[t];
        float inv = g_inv[row];
        float4 r;
        r.x = (a0.x + a1.x + a2.x + a3.x) * inv;
        r.y = (a0.y + a1.y + a2.y + a3.y) * inv;
        r.z = (a0.z + a1.z + a2.z + a3.z) * inv;
        r.w = (a0.w + a1.w + a2.w + a3.w) * inv;
        ((float4*)(out + ((size_t)row << 8)))[t] = r;
    }
}

// ----------------- 7. width-1 aggregation with fused epilogues -----------------
// mode 0: out[row] = relu(agg1(y)[row] + w0 + g_yr[row])
// mode 1: out[row] = sigmoid(agg1(y)[row]*w0 + w1 + y[row]*w2 + g_sc[row])
template <int MODE>
__global__ void __launch_bounds__(256) k_agg1f(const float* __restrict__ y,
                                               const float* __restrict__ w0,
                                               const float* __restrict__ w1,
                                               const float* __restrict__ w2,
                                               float* __restrict__ out) {
    __shared__ float sred[8];
    int row = blockIdx.x, t = threadIdx.x;
    unsigned m = g_adj[row * NWORD + t];
    int base = t << 5;
    float acc = 0.f;
    while (m) {
        int b = __ffs(m) - 1;
        m &= m - 1;
        acc += __ldg(&y[base + b]);
    }
    #pragma unroll
    for (int o = 16; o; o >>= 1) acc += __shfl_xor_sync(0xffffffffu, acc, o);
    if ((t & 31) == 0) sred[t >> 5] = acc;
    __syncthreads();
    if (t == 0) {
        float v = 0.f;
        #pragma unroll
        for (int i = 0; i < 8; i++) v += sred[i];
        float a = v * g_inv[row];
        if (MODE == 0) {
            out[row] = fmaxf(a + w0[0] + g_yr[row], 0.f);
        } else {
            float o = a * w0[0] + w1[0] + y[row] * w2[0] + g_sc[row];
            out[row] = 1.0f / (1.0f + expf(-o));
        }
    }
}

// ----------------- 8. three fused matvecs -----------------
__global__ void k_matvec3(const float* __restrict__ h,
                          const float* __restrict__ wl, const float* __restrict__ wr,
                          const float* __restrict__ wsc, const float* __restrict__ oscb) {
    int gw   = (blockIdx.x * blockDim.x + threadIdx.x) >> 5;   // one warp per row
    int lane = threadIdx.x & 31;
    if (gw >= NN) return;
    const float* hr = h + (size_t)gw * HDIM;
    float sl = 0.f, sr = 0.f, ss = 0.f;
    #pragma unroll
    for (int u = 0; u < HDIM / 32; u++) {
        int idx = lane + u * 32;
        float v = hr[idx];
        sl += v * __ldg(&wl[idx]);
        sr += v * __ldg(&wr[idx]);
        ss += v * __ldg(&wsc[idx]);
    }
    #pragma unroll
    for (int o = 16; o; o >>= 1) {
        sl += __shfl_xor_sync(0xffffffffu, sl, o);
        sr += __shfl_xor_sync(0xffffffffu, sr, o);
        ss += __shfl_xor_sync(0xffffffffu, ss, o);
    }
    if (lane == 0) {
        g_yl[gw] = sl;
        g_yr[gw] = sr;
        g_sc[gw] = ss + oscb[0];
    }
}

// ========================= launch =========================
extern "C" void kernel_launch(void* const* d_in, const int* in_sizes, int n_in,
                              void* d_out, int out_size) {
    const float* x     = (const float*)d_in[0];
    const float* w_in  = (const float*)d_in[1];
    const float* b_in  = (const float*)d_in[2];
    const float* h1_wl = (const float*)d_in[3];
    const float* h1_bl = (const float*)d_in[4];
    const float* h1_wr = (const float*)d_in[5];
    const float* h2_wl = (const float*)d_in[6];
    const float* h2_bl = (const float*)d_in[7];
    const float* h2_wr = (const float*)d_in[8];
    const float* o1_wl = (const float*)d_in[9];
    const float* o1_bl = (const float*)d_in[10];
    const float* o1_wr = (const float*)d_in[11];
    const float* o2_wl = (const float*)d_in[12];
    const float* o2_bl = (const float*)d_in[13];
    const float* o2_wr = (const float*)d_in[14];
    const float* osc_w = (const float*)d_in[15];
    const float* osc_b = (const float*)d_in[16];
    float* out = (float*)d_out;

    // resolve scratch addresses
    float  *p_h0, *p_h1, *p_h2, *p_agg, *p_yl, *p_o1;
    __half *p_h0f, *p_h1f;
    cudaGetSymbolAddress((void**)&p_h0,  g_h0);
    cudaGetSymbolAddress((void**)&p_h1,  g_h1);
    cudaGetSymbolAddress((void**)&p_h2,  g_h2);
    cudaGetSymbolAddress((void**)&p_h0f, g_h0f);
    cudaGetSymbolAddress((void**)&p_h1f, g_h1f);
    cudaGetSymbolAddress((void**)&p_agg, g_agg);
    cudaGetSymbolAddress((void**)&p_yl,  g_yl);
    cudaGetSymbolAddress((void**)&p_o1,  g_o1v);

    // 1) normalize
    k_normalize<<<NN, DIN>>>(x);
    // 2) similarity matrix, upper-triangle tiles only
    dim3 gs(NTILE, NTILE);
    k_simgemm_sym<<<gs, 256>>>();
    // 3) exact quantile: 3-pass radix select; pass 1 compacts candidates (block-staged)
    k_init_sel<<<1, 256>>>();
    k_hist<0><<<1040, 256>>>();
    k_scan<<<1, 1024>>>(8192, 19);
    k_hist<1><<<1040, 256>>>();
    k_scan<<<1, 1024>>>(8192, 6);
    k_hist2c<<<1040, 256>>>();
    k_scan<<<1, 1024>>>(64, 0);
    // 4) adjacency from upper tiles (direct + bit-transposed mirror), then degrees
    k_adj_tile<<<NUT, 256>>>();
    k_deg<<<NN * 32 / 256, 256>>>();
    // 5) h0 = relu(x @ w_in + b_in)   (+ fp16 copy for aggregation)
    dim3 gd(NN / 128, HDIM / 64);
    k_sage<<<gd, 256>>>(x, w_in, DIN, nullptr, nullptr, 0, b_in, nullptr, p_h0, p_h0f, 1);
    // 6) h1 = relu(agg(h0) @ h1_wl + h1_bl + h0 @ h1_wr)
    k_agg<<<NN, 256>>>(p_h0f, p_agg);
    k_sage<<<gd, 256>>>(p_agg, h1_wl, HDIM, p_h0, h1_wr, HDIM, h1_bl, nullptr, p_h1, p_h1f, 1);
    // 7) h2 = relu(agg(h1) @ h2_wl + h2_bl + h1 @ h2_wr + h0)
    k_agg<<<NN, 256>>>(p_h1f, p_agg);
    k_sage<<<gd, 256>>>(p_agg, h2_wl, HDIM, p_h1, h2_wr, HDIM, h2_bl, p_h0, p_h2, nullptr, 1);
    // 8) output heads: agg(h2)@wl == agg(h2@wl)  (linearity) -> scalar aggregations
    k_matvec3<<<NN * 32 / 256, 256>>>(p_h2, o1_wl, o1_wr, osc_w, osc_b);
    // o1 = relu(agg1(yl) + o1_bl + yr)          (fused epilogue)
    k_agg1f<0><<<NN, 256>>>(p_yl, o1_bl, nullptr, nullptr, p_o1);
    // out = sigmoid(agg1(o1)*o2_wl + o2_bl + o1*o2_wr + sc)   (fused epilogue)
    k_agg1f<1><<<NN, 256>>>(p_o1, o2_wl, o2_bl, o2_wr, out);
}